// round 12
// baseline (speedup 1.0000x reference)
#include <cuda_runtime.h>
#include <cuda_fp16.h>
#include <cstdint>

#define B_ 8
#define S_ 2048
#define E_ 512

// ---------------- scratch (__device__ globals; no allocs allowed) ----------
__device__ __align__(16) __half g_xhi[(size_t)B_ * S_ * E_];
__device__ __align__(16) __half g_qhi[(size_t)B_ * S_ * E_];
__device__ __align__(16) __half g_khi[(size_t)B_ * S_ * E_];
__device__ __align__(16) __half g_vthi[(size_t)B_ * E_ * S_];  // [B][E][S]
__device__ __align__(16) __half g_phi[(size_t)B_ * S_ * S_];   // unnormalized exp
__device__ __align__(16) __half g_wqh[E_ * E_];
__device__ __align__(16) __half g_wkh[E_ * E_];
__device__ __align__(16) __half g_wvh[E_ * E_];
__device__ __align__(16) float g_psum[16 * B_ * S_];           // [tileN][B*S]
__device__ __align__(16) float g_Z[B_ * S_];                   // row sums

// ---------------- helpers ---------------------------------------------------
__device__ __forceinline__ uint32_t smem_u32(const void* p) {
    uint32_t a;
    asm("{ .reg .u64 t; cvta.to.shared.u64 t, %1; cvt.u32.u64 %0, t; }"
        : "=r"(a) : "l"(p));
    return a;
}
__device__ __forceinline__ void cp16(uint32_t dst, const void* src) {
    asm volatile("cp.async.cg.shared.global [%0], [%1], 16;"
                 :: "r"(dst), "l"(src) : "memory");
}
__device__ __forceinline__ void cp_commit() {
    asm volatile("cp.async.commit_group;" ::: "memory");
}
template <int N>
__device__ __forceinline__ void cp_wait() {
    asm volatile("cp.async.wait_group %0;" :: "n"(N) : "memory");
}
__device__ __forceinline__ void ldm_x4(uint32_t& r0, uint32_t& r1, uint32_t& r2,
                                       uint32_t& r3, uint32_t addr) {
    asm volatile("ldmatrix.sync.aligned.m8n8.x4.shared.b16 {%0,%1,%2,%3}, [%4];"
                 : "=r"(r0), "=r"(r1), "=r"(r2), "=r"(r3) : "r"(addr));
}
__device__ __forceinline__ void mma16816(float* d, const uint32_t* a, const uint32_t* b) {
    asm volatile("mma.sync.aligned.m16n8k16.row.col.f32.f16.f16.f32 "
                 "{%0,%1,%2,%3}, {%4,%5,%6,%7}, {%8,%9}, {%0,%1,%2,%3};"
                 : "+f"(d[0]), "+f"(d[1]), "+f"(d[2]), "+f"(d[3])
                 : "r"(a[0]), "r"(a[1]), "r"(a[2]), "r"(a[3]), "r"(b[0]), "r"(b[1]));
}

// ---------------------------------------------------------------------------
// NT GEMM, pure fp16 MMA: C-tile = A[M,K] . B[N,K]^T (+ epilogue).
// Block 128x128, 8 warps (4m x 2n), warp tile 32x64, KC=64, double-buffered
// smem + register-double-buffered fragments (LDSM(next) overlaps HMMA(cur)).
// EPI: 4 = +bias -> fp16 outH
//      5 = p = (mask>0 ? 0 : exp(scale*s)) -> fp16 outH; row partial sums -> psum
//      6 = acc / Z[row] -> fp32 C
//      7 = +bias -> fp16, transposed into outH as [E][S] tile (V projection)
// ---------------------------------------------------------------------------
#define KC 64
#define TSTR 72                        // padded halfs per smem row (64 + 8)
#define TILE_B (128 * TSTR * 2)        // 18432 bytes per tile
#define STAGE_B (2 * TILE_B)           // 36864
#define SMEM_SZ (2 * STAGE_B)          // 73728

template <int EPI>
__global__ void __launch_bounds__(256, 2)
gemm_f16s(const __half* __restrict__ A, const __half* __restrict__ Bm,
          const float* __restrict__ bias, const int* __restrict__ mask,
          float* __restrict__ C, __half* __restrict__ outH,
          float* __restrict__ psum, const float* __restrict__ zrow,
          int K, int N, long sA, long sB, long sC, float scale)
{
    extern __shared__ __align__(16) char sm[];
    const uint32_t sb = smem_u32(sm);

    const int tid  = threadIdx.x;
    const int lane = tid & 31;
    const int wid  = tid >> 5;
    const int warp_m = wid & 3;
    const int warp_n = wid >> 2;

    const int bz = blockIdx.z;
    A  += (long)bz * sA;
    Bm += (long)bz * sB;
    if (EPI == 5) mask += (long)bz * sC;
    if (EPI == 6) C += (long)bz * sC;
    if (EPI == 4 || EPI == 5) outH += (long)bz * sC;
    const int bm = blockIdx.y * 128;
    const int bn = blockIdx.x * 128;

    const int lr = tid >> 3;           // row 0..31 (4 passes -> 128)
    const int ls = tid & 7;            // 16B segment (8 per 128B row)
    auto load_chunk = [&](int c) {
        const uint32_t st = sb + (uint32_t)(c & 1) * STAGE_B;
        const int k0 = c * KC;
#pragma unroll
        for (int t = 0; t < 4; ++t) {
            const int r = lr + t * 32;
            const uint32_t so = (uint32_t)(r * (TSTR * 2) + ls * 16);
            cp16(st + so,          A  + (long)(bm + r) * K + k0 + ls * 8);
            cp16(st + TILE_B + so, Bm + (long)(bn + r) * K + k0 + ls * 8);
        }
        cp_commit();
    };

    float acc[2][8][4];
#pragma unroll
    for (int mi = 0; mi < 2; ++mi)
#pragma unroll
        for (int ni = 0; ni < 8; ++ni)
#pragma unroll
            for (int r = 0; r < 4; ++r) acc[mi][ni][r] = 0.0f;

    const int quad = lane >> 3, lm8 = lane & 7;
    const int a_row = warp_m * 32 + lm8 + (quad & 1) * 8;
    const int a_col = (quad >> 1) * 8;
    const int b_row = warp_n * 64 + lm8 + (quad >> 1) * 8;
    const int b_col = (quad & 1) * 8;

    // fragment loader for one ks-step into the given register buffer
    auto ldfrags = [&](uint32_t st, int ks, uint32_t (*ah)[4], uint32_t (*bh)[2]) {
#pragma unroll
        for (int mi = 0; mi < 2; ++mi) {
            const uint32_t ao =
                (uint32_t)(((a_row + mi * 16) * TSTR + a_col + ks) * 2);
            ldm_x4(ah[mi][0], ah[mi][1], ah[mi][2], ah[mi][3], st + ao);
        }
#pragma unroll
        for (int np = 0; np < 4; ++np) {
            const uint32_t bo =
                (uint32_t)(((b_row + np * 16) * TSTR + b_col + ks) * 2);
            ldm_x4(bh[2 * np][0], bh[2 * np][1], bh[2 * np + 1][0], bh[2 * np + 1][1],
                   st + TILE_B + bo);
        }
    };

    const int nch = K / KC;
    load_chunk(0);
    for (int c = 0; c < nch; ++c) {
        if (c + 1 < nch) { load_chunk(c + 1); cp_wait<1>(); }
        else             { cp_wait<0>(); }
        __syncthreads();

        const uint32_t st = sb + (uint32_t)(c & 1) * STAGE_B;
        uint32_t ah[2][2][4], bh[2][8][2];
        ldfrags(st, 0, ah[0], bh[0]);
#pragma unroll
        for (int i = 0; i < 4; ++i) {
            const int cur = i & 1;
            if (i < 3) ldfrags(st, (i + 1) * 16, ah[cur ^ 1], bh[cur ^ 1]);
#pragma unroll
            for (int mi = 0; mi < 2; ++mi)
#pragma unroll
                for (int ni = 0; ni < 8; ++ni)
                    mma16816(acc[mi][ni], ah[cur][mi], bh[cur][ni]);
        }
        __syncthreads();
    }

    // ---- epilogue ----
    if (EPI == 7) {
        // V projection: +bias, fp16, then transpose tile via smem and write
        // Vt[B][E][S] coalescedly. buf is [128 rows][136 halfs].
        __half* buf = reinterpret_cast<__half*>(sm);
#pragma unroll
        for (int mi = 0; mi < 2; ++mi)
#pragma unroll
            for (int ni = 0; ni < 8; ++ni) {
                const int rl = warp_m * 32 + mi * 16 + (lane >> 2);
                const int cl = warp_n * 64 + ni * 8 + (lane & 3) * 2;
                const float2 bb = *reinterpret_cast<const float2*>(&bias[bn + cl]);
                const float c0 = acc[mi][ni][0] + bb.x;
                const float c1 = acc[mi][ni][1] + bb.y;
                const float c2 = acc[mi][ni][2] + bb.x;
                const float c3 = acc[mi][ni][3] + bb.y;
                *reinterpret_cast<__half2*>(&buf[rl * 136 + cl]) =
                    __halves2half2(__float2half_rn(c0), __float2half_rn(c1));
                *reinterpret_cast<__half2*>(&buf[(rl + 8) * 136 + cl]) =
                    __halves2half2(__float2half_rn(c2), __float2half_rn(c3));
            }
        __syncthreads();
        const int b  = bm / S_;
        const int s0 = bm % S_;
#pragma unroll
        for (int i = 0; i < 32; ++i) {
            const int idx = tid + i * 256;     // 8192 half2 units
            const int e  = idx >> 6;           // 0..127
            const int sp = idx & 63;           // half2 index along s
            const __half2 v = __halves2half2(buf[(2 * sp) * 136 + e],
                                             buf[(2 * sp + 1) * 136 + e]);
            *reinterpret_cast<__half2*>(
                &outH[((long)b * E_ + bn + e) * S_ + s0 + 2 * sp]) = v;
        }
        return;
    }

    float invz[2][2];
    if (EPI == 6) {
#pragma unroll
        for (int mi = 0; mi < 2; ++mi)
#pragma unroll
            for (int j = 0; j < 2; ++j) {
                const int row = bm + warp_m * 32 + mi * 16 + (lane >> 2) + j * 8;
                invz[mi][j] = 1.0f / __ldg(&zrow[(long)bz * S_ + row]);
            }
    }
    float rsum[2][2] = {{0.0f, 0.0f}, {0.0f, 0.0f}};

#pragma unroll
    for (int mi = 0; mi < 2; ++mi)
#pragma unroll
        for (int ni = 0; ni < 8; ++ni) {
            const int row0 = bm + warp_m * 32 + mi * 16 + (lane >> 2);
            const int col0 = bn + warp_n * 64 + ni * 8 + (lane & 3) * 2;
            float c0 = acc[mi][ni][0], c1 = acc[mi][ni][1];
            float c2 = acc[mi][ni][2], c3 = acc[mi][ni][3];
            if (EPI == 4) {
                const float2 bb = *reinterpret_cast<const float2*>(&bias[col0]);
                c0 += bb.x; c1 += bb.y; c2 += bb.x; c3 += bb.y;
            }
            if (EPI == 5) {
                const int2 ma = *reinterpret_cast<const int2*>(&mask[(long)row0 * N + col0]);
                const int2 mb = *reinterpret_cast<const int2*>(&mask[(long)(row0 + 8) * N + col0]);
                c0 = (ma.x > 0) ? 0.0f : __expf(scale * c0);
                c1 = (ma.y > 0) ? 0.0f : __expf(scale * c1);
                c2 = (mb.x > 0) ? 0.0f : __expf(scale * c2);
                c3 = (mb.y > 0) ? 0.0f : __expf(scale * c3);
                rsum[mi][0] += c0 + c1;
                rsum[mi][1] += c2 + c3;
            }
            if (EPI == 6) {
                c0 *= invz[mi][0]; c1 *= invz[mi][0];
                c2 *= invz[mi][1]; c3 *= invz[mi][1];
            }
            if (EPI == 4 || EPI == 5) {
                *reinterpret_cast<__half2*>(&outH[(long)row0 * N + col0]) =
                    __halves2half2(__float2half_rn(c0), __float2half_rn(c1));
                *reinterpret_cast<__half2*>(&outH[(long)(row0 + 8) * N + col0]) =
                    __halves2half2(__float2half_rn(c2), __float2half_rn(c3));
            } else {
                *reinterpret_cast<float2*>(&C[(long)row0 * N + col0]) = make_float2(c0, c1);
                *reinterpret_cast<float2*>(&C[(long)(row0 + 8) * N + col0]) = make_float2(c2, c3);
            }
        }

    if (EPI == 5) {
#pragma unroll
        for (int mi = 0; mi < 2; ++mi)
#pragma unroll
            for (int j = 0; j < 2; ++j) {
                rsum[mi][j] += __shfl_xor_sync(0xFFFFFFFFu, rsum[mi][j], 1);
                rsum[mi][j] += __shfl_xor_sync(0xFFFFFFFFu, rsum[mi][j], 2);
            }
        float* rowbuf = reinterpret_cast<float*>(sm);
        if (tid < 128) rowbuf[tid] = 0.0f;
        __syncthreads();
        if ((lane & 3) == 0) {
#pragma unroll
            for (int mi = 0; mi < 2; ++mi)
#pragma unroll
                for (int j = 0; j < 2; ++j)
                    atomicAdd(&rowbuf[warp_m * 32 + mi * 16 + (lane >> 2) + j * 8],
                              rsum[mi][j]);
        }
        __syncthreads();
        if (tid < 128)
            psum[(long)blockIdx.x * (B_ * S_) + (long)bz * S_ + bm + tid] = rowbuf[tid];
    }
}

// ---------------------------------------------------------------------------
// Z[row] = sum over 16 tile partials
// ---------------------------------------------------------------------------
__global__ void __launch_bounds__(256)
zreduce_kernel(const float* __restrict__ psum, float* __restrict__ z)
{
    const int i = blockIdx.x * 256 + threadIdx.x;
    float s = 0.0f;
#pragma unroll
    for (int k = 0; k < 16; ++k) s += psum[(long)k * (B_ * S_) + i];
    z[i] = s;
}

// ---------------------------------------------------------------------------
// fp32 -> fp16 casts: big x, and the 3 weights batched in one launch
// ---------------------------------------------------------------------------
__global__ void __launch_bounds__(256)
split_hi_kernel(const float* __restrict__ src, __half* __restrict__ hi, long n4)
{
    const long i = (long)blockIdx.x * blockDim.x + threadIdx.x;
    if (i >= n4) return;
    const float4 v = reinterpret_cast<const float4*>(src)[i];
    __half2* hi2 = reinterpret_cast<__half2*>(hi);
    hi2[2 * i]     = __halves2half2(__float2half_rn(v.x), __float2half_rn(v.y));
    hi2[2 * i + 1] = __halves2half2(__float2half_rn(v.z), __float2half_rn(v.w));
}

__global__ void __launch_bounds__(256)
split3_kernel(const float* __restrict__ w0, const float* __restrict__ w1,
              const float* __restrict__ w2, __half* __restrict__ h0,
              __half* __restrict__ h1, __half* __restrict__ h2, long n4)
{
    const long i = (long)blockIdx.x * blockDim.x + threadIdx.x;
    if (i >= n4) return;
    const float* src = (blockIdx.y == 0) ? w0 : (blockIdx.y == 1) ? w1 : w2;
    __half* dst      = (blockIdx.y == 0) ? h0 : (blockIdx.y == 1) ? h1 : h2;
    const float4 v = reinterpret_cast<const float4*>(src)[i];
    __half2* hi2 = reinterpret_cast<__half2*>(dst);
    hi2[2 * i]     = __halves2half2(__float2half_rn(v.x), __float2half_rn(v.y));
    hi2[2 * i + 1] = __halves2half2(__float2half_rn(v.z), __float2half_rn(v.w));
}

// ---------------------------------------------------------------------------
extern "C" void kernel_launch(void* const* d_in, const int* in_sizes, int n_in,
                              void* d_out, int out_size)
{
    const float* x    = (const float*)d_in[0];
    const int*   mask = (const int*)  d_in[1];
    const float* wq   = (const float*)d_in[2];
    const float* bq   = (const float*)d_in[3];
    const float* wk   = (const float*)d_in[4];
    const float* bk   = (const float*)d_in[5];
    const float* wv   = (const float*)d_in[6];
    const float* bv   = (const float*)d_in[7];
    float* out = (float*)d_out;

    float *psum, *gz;
    cudaGetSymbolAddress((void**)&psum, g_psum);
    cudaGetSymbolAddress((void**)&gz, g_Z);
    __half *xhi, *qhi, *khi, *vthi, *phi, *wqh, *wkh, *wvh;
    cudaGetSymbolAddress((void**)&xhi, g_xhi);
    cudaGetSymbolAddress((void**)&qhi, g_qhi);
    cudaGetSymbolAddress((void**)&khi, g_khi);
    cudaGetSymbolAddress((void**)&vthi, g_vthi);
    cudaGetSymbolAddress((void**)&phi, g_phi);
    cudaGetSymbolAddress((void**)&wqh, g_wqh);
    cudaGetSymbolAddress((void**)&wkh, g_wkh);
    cudaGetSymbolAddress((void**)&wvh, g_wvh);

    // dynamic smem > 48KB needs opt-in
    cudaFuncSetAttribute(gemm_f16s<4>, cudaFuncAttributeMaxDynamicSharedMemorySize, SMEM_SZ);
    cudaFuncSetAttribute(gemm_f16s<5>, cudaFuncAttributeMaxDynamicSharedMemorySize, SMEM_SZ);
    cudaFuncSetAttribute(gemm_f16s<6>, cudaFuncAttributeMaxDynamicSharedMemorySize, SMEM_SZ);
    cudaFuncSetAttribute(gemm_f16s<7>, cudaFuncAttributeMaxDynamicSharedMemorySize, SMEM_SZ);

    const long nx = (long)B_ * S_ * E_;
    const long nw = (long)E_ * E_;

    // 1) fp16 casts
    split_hi_kernel<<<(unsigned)((nx / 4 + 255) / 256), 256>>>(x, xhi, nx / 4);
    split3_kernel<<<dim3((unsigned)((nw / 4 + 255) / 256), 3), 256>>>(
        wq, wk, wv, wqh, wkh, wvh, nw / 4);

    // 2) projections (1-term): Q,K -> fp16; V -> fp16 transposed (fused)
    const dim3 gproj(E_ / 128, (B_ * S_) / 128, 1);
    gemm_f16s<4><<<gproj, 256, SMEM_SZ>>>(xhi, wqh, bq, nullptr, nullptr, qhi,
                                          nullptr, nullptr, E_, E_, 0, 0, 0, 1.0f);
    gemm_f16s<4><<<gproj, 256, SMEM_SZ>>>(xhi, wkh, bk, nullptr, nullptr, khi,
                                          nullptr, nullptr, E_, E_, 0, 0, 0, 1.0f);
    gemm_f16s<7><<<gproj, 256, SMEM_SZ>>>(xhi, wvh, bv, nullptr, nullptr, vthi,
                                          nullptr, nullptr, E_, E_, 0, 0, 0, 1.0f);

    // 3) scores + mask + max-free exp -> unnormalized P (fp16) + row partials
    const float scale = 0.044194173824159216f;  // 512^-0.5
    const dim3 gsc(S_ / 128, S_ / 128, B_);
    gemm_f16s<5><<<gsc, 256, SMEM_SZ>>>(qhi, khi, nullptr, mask, nullptr, phi,
                                        psum, nullptr, E_, S_,
                                        (long)S_ * E_, (long)S_ * E_,
                                        (long)S_ * S_, scale);

    // 4) Z[row] = sum of partials
    zreduce_kernel<<<(B_ * S_) / 256, 256>>>(psum, gz);

    // 5) out = (P~ . Vt^T) / Z
    const dim3 gpv(E_ / 128, S_ / 128, B_);
    gemm_f16s<6><<<gpv, 256, SMEM_SZ>>>(phi, vthi, nullptr, nullptr, out, nullptr,
                                        nullptr, gz, S_, E_,
                                        (long)S_ * S_, (long)E_ * S_,
                                        (long)S_ * E_, 1.0f);
}

// round 13
// speedup vs baseline: 1.0738x; 1.0738x over previous
#include <cuda_runtime.h>
#include <cuda_fp16.h>
#include <cstdint>

#define B_ 8
#define S_ 2048
#define E_ 512

// ---------------- scratch (__device__ globals; no allocs allowed) ----------
__device__ __align__(16) __half g_xhi[(size_t)B_ * S_ * E_];
__device__ __align__(16) __half g_qhi[(size_t)B_ * S_ * E_];
__device__ __align__(16) __half g_khi[(size_t)B_ * S_ * E_];
__device__ __align__(16) __half g_vthi[(size_t)B_ * E_ * S_];  // [B][E][S]
__device__ __align__(16) __half g_phi[(size_t)B_ * S_ * S_];   // unnormalized exp
__device__ __align__(16) __half g_wqh[E_ * E_];
__device__ __align__(16) __half g_wkh[E_ * E_];
__device__ __align__(16) __half g_wvh[E_ * E_];
__device__ __align__(16) float g_psum[16 * B_ * S_];           // [tileN][B*S]
__device__ __align__(16) float g_Z[B_ * S_];                   // row sums

// ---------------- helpers ---------------------------------------------------
__device__ __forceinline__ uint32_t smem_u32(const void* p) {
    uint32_t a;
    asm("{ .reg .u64 t; cvta.to.shared.u64 t, %1; cvt.u32.u64 %0, t; }"
        : "=r"(a) : "l"(p));
    return a;
}
__device__ __forceinline__ void cp16(uint32_t dst, const void* src) {
    asm volatile("cp.async.cg.shared.global [%0], [%1], 16;"
                 :: "r"(dst), "l"(src) : "memory");
}
__device__ __forceinline__ void cp_commit() {
    asm volatile("cp.async.commit_group;" ::: "memory");
}
template <int N>
__device__ __forceinline__ void cp_wait() {
    asm volatile("cp.async.wait_group %0;" :: "n"(N) : "memory");
}
__device__ __forceinline__ void ldm_x4(uint32_t& r0, uint32_t& r1, uint32_t& r2,
                                       uint32_t& r3, uint32_t addr) {
    asm volatile("ldmatrix.sync.aligned.m8n8.x4.shared.b16 {%0,%1,%2,%3}, [%4];"
                 : "=r"(r0), "=r"(r1), "=r"(r2), "=r"(r3) : "r"(addr));
}
__device__ __forceinline__ void mma16816(float* d, const uint32_t* a, const uint32_t* b) {
    asm volatile("mma.sync.aligned.m16n8k16.row.col.f32.f16.f16.f32 "
                 "{%0,%1,%2,%3}, {%4,%5,%6,%7}, {%8,%9}, {%0,%1,%2,%3};"
                 : "+f"(d[0]), "+f"(d[1]), "+f"(d[2]), "+f"(d[3])
                 : "r"(a[0]), "r"(a[1]), "r"(a[2]), "r"(a[3]), "r"(b[0]), "r"(b[1]));
}

// ---------------------------------------------------------------------------
// NT GEMM, pure fp16 MMA: C-tile = A[M,K] . B[N,K]^T (+ epilogue).
// Block 128x128, 8 warps (4m x 2n), warp tile 32x64, KC=64, double-buffered.
// EPI: 4 = +bias -> fp16 outH
//      5 = p = (mask>0 ? 0 : exp(scale*s)) -> fp16 outH; row partial sums -> psum
//      6 = acc / Z[row] -> fp32 C
//      7 = +bias -> fp16, transposed into outH as [E][S] tile (V projection)
//      8 = QK merged: blockIdx.z selects (Bm0,bias0,out0) / (Bm1,bias1,out1)
// ---------------------------------------------------------------------------
#define KC 64
#define TSTR 72                        // padded halfs per smem row (64 + 8)
#define TILE_B (128 * TSTR * 2)        // 18432 bytes per tile
#define STAGE_B (2 * TILE_B)           // 36864
#define SMEM_SZ (2 * STAGE_B)          // 73728

template <int EPI>
__global__ void __launch_bounds__(256)
gemm_f16s(const __half* __restrict__ A, const __half* __restrict__ Bm,
          const float* __restrict__ bias, const int* __restrict__ mask,
          float* __restrict__ C, __half* __restrict__ outH,
          float* __restrict__ psum, const float* __restrict__ zrow,
          const __half* __restrict__ Bm1, const float* __restrict__ bias1,
          __half* __restrict__ outH1,
          int K, int N, long sA, long sB, long sC, float scale)
{
    extern __shared__ __align__(16) char sm[];
    const uint32_t sb = smem_u32(sm);

    const int tid  = threadIdx.x;
    const int lane = tid & 31;
    const int wid  = tid >> 5;
    const int warp_m = wid & 3;
    const int warp_n = wid >> 2;

    const int bz = blockIdx.z;
    if (EPI == 8) {
        // merged Q/K projection: z selects weight/bias/output (no batch offset)
        if (bz == 1) { Bm = Bm1; bias = bias1; outH = outH1; }
    } else {
        A  += (long)bz * sA;
        Bm += (long)bz * sB;
        if (EPI == 5) mask += (long)bz * sC;
        if (EPI == 6) C += (long)bz * sC;
        if (EPI == 5) outH += (long)bz * sC;
    }
    const int bm = blockIdx.y * 128;
    const int bn = blockIdx.x * 128;

    const int lr = tid >> 3;           // row 0..31 (4 passes -> 128)
    const int ls = tid & 7;            // 16B segment (8 per 128B row)
    auto load_chunk = [&](int c) {
        const uint32_t st = sb + (uint32_t)(c & 1) * STAGE_B;
        const int k0 = c * KC;
#pragma unroll
        for (int t = 0; t < 4; ++t) {
            const int r = lr + t * 32;
            const uint32_t so = (uint32_t)(r * (TSTR * 2) + ls * 16);
            cp16(st + so,          A  + (long)(bm + r) * K + k0 + ls * 8);
            cp16(st + TILE_B + so, Bm + (long)(bn + r) * K + k0 + ls * 8);
        }
        cp_commit();
    };

    float acc[2][8][4];
#pragma unroll
    for (int mi = 0; mi < 2; ++mi)
#pragma unroll
        for (int ni = 0; ni < 8; ++ni)
#pragma unroll
            for (int r = 0; r < 4; ++r) acc[mi][ni][r] = 0.0f;

    const int quad = lane >> 3, lm8 = lane & 7;
    const int a_row = warp_m * 32 + lm8 + (quad & 1) * 8;
    const int a_col = (quad >> 1) * 8;
    const int b_row = warp_n * 64 + lm8 + (quad >> 1) * 8;
    const int b_col = (quad & 1) * 8;

    const int nch = K / KC;
    load_chunk(0);
    for (int c = 0; c < nch; ++c) {
        if (c + 1 < nch) { load_chunk(c + 1); cp_wait<1>(); }
        else             { cp_wait<0>(); }
        __syncthreads();

        const uint32_t st = sb + (uint32_t)(c & 1) * STAGE_B;
#pragma unroll
        for (int ks = 0; ks < KC; ks += 16) {
            uint32_t ah[2][4], bh[8][2];
#pragma unroll
            for (int mi = 0; mi < 2; ++mi) {
                const uint32_t ao =
                    (uint32_t)(((a_row + mi * 16) * TSTR + a_col + ks) * 2);
                ldm_x4(ah[mi][0], ah[mi][1], ah[mi][2], ah[mi][3], st + ao);
            }
#pragma unroll
            for (int np = 0; np < 4; ++np) {
                const uint32_t bo =
                    (uint32_t)(((b_row + np * 16) * TSTR + b_col + ks) * 2);
                ldm_x4(bh[2 * np][0], bh[2 * np][1], bh[2 * np + 1][0], bh[2 * np + 1][1],
                       st + TILE_B + bo);
            }
#pragma unroll
            for (int mi = 0; mi < 2; ++mi)
#pragma unroll
                for (int ni = 0; ni < 8; ++ni)
                    mma16816(acc[mi][ni], ah[mi], bh[ni]);
        }
        __syncthreads();
    }

    // ---- epilogue ----
    if (EPI == 7) {
        // V projection: +bias, fp16, then transpose tile via smem and write
        // Vt[B][E][S] coalescedly. buf is [128 rows][136 halfs].
        __half* buf = reinterpret_cast<__half*>(sm);
#pragma unroll
        for (int mi = 0; mi < 2; ++mi)
#pragma unroll
            for (int ni = 0; ni < 8; ++ni) {
                const int rl = warp_m * 32 + mi * 16 + (lane >> 2);
                const int cl = warp_n * 64 + ni * 8 + (lane & 3) * 2;
                const float2 bb = *reinterpret_cast<const float2*>(&bias[bn + cl]);
                const float c0 = acc[mi][ni][0] + bb.x;
                const float c1 = acc[mi][ni][1] + bb.y;
                const float c2 = acc[mi][ni][2] + bb.x;
                const float c3 = acc[mi][ni][3] + bb.y;
                *reinterpret_cast<__half2*>(&buf[rl * 136 + cl]) =
                    __halves2half2(__float2half_rn(c0), __float2half_rn(c1));
                *reinterpret_cast<__half2*>(&buf[(rl + 8) * 136 + cl]) =
                    __halves2half2(__float2half_rn(c2), __float2half_rn(c3));
            }
        __syncthreads();
        const int b  = bm / S_;
        const int s0 = bm % S_;
#pragma unroll
        for (int i = 0; i < 32; ++i) {
            const int idx = tid + i * 256;     // 8192 half2 units
            const int e  = idx >> 6;           // 0..127
            const int sp = idx & 63;           // half2 index along s
            const __half2 v = __halves2half2(buf[(2 * sp) * 136 + e],
                                             buf[(2 * sp + 1) * 136 + e]);
            *reinterpret_cast<__half2*>(
                &outH[((long)b * E_ + bn + e) * S_ + s0 + 2 * sp]) = v;
        }
        return;
    }

    float invz[2][2];
    if (EPI == 6) {
#pragma unroll
        for (int mi = 0; mi < 2; ++mi)
#pragma unroll
            for (int j = 0; j < 2; ++j) {
                const int row = bm + warp_m * 32 + mi * 16 + (lane >> 2) + j * 8;
                invz[mi][j] = 1.0f / __ldg(&zrow[(long)bz * S_ + row]);
            }
    }
    float rsum[2][2] = {{0.0f, 0.0f}, {0.0f, 0.0f}};

#pragma unroll
    for (int mi = 0; mi < 2; ++mi)
#pragma unroll
        for (int ni = 0; ni < 8; ++ni) {
            const int row0 = bm + warp_m * 32 + mi * 16 + (lane >> 2);
            const int col0 = bn + warp_n * 64 + ni * 8 + (lane & 3) * 2;
            float c0 = acc[mi][ni][0], c1 = acc[mi][ni][1];
            float c2 = acc[mi][ni][2], c3 = acc[mi][ni][3];
            if (EPI == 4 || EPI == 8) {
                const float2 bb = *reinterpret_cast<const float2*>(&bias[col0]);
                c0 += bb.x; c1 += bb.y; c2 += bb.x; c3 += bb.y;
            }
            if (EPI == 5) {
                const int2 ma = *reinterpret_cast<const int2*>(&mask[(long)row0 * N + col0]);
                const int2 mb = *reinterpret_cast<const int2*>(&mask[(long)(row0 + 8) * N + col0]);
                c0 = (ma.x > 0) ? 0.0f : __expf(scale * c0);
                c1 = (ma.y > 0) ? 0.0f : __expf(scale * c1);
                c2 = (mb.x > 0) ? 0.0f : __expf(scale * c2);
                c3 = (mb.y > 0) ? 0.0f : __expf(scale * c3);
                rsum[mi][0] += c0 + c1;
                rsum[mi][1] += c2 + c3;
            }
            if (EPI == 6) {
                c0 *= invz[mi][0]; c1 *= invz[mi][0];
                c2 *= invz[mi][1]; c3 *= invz[mi][1];
            }
            if (EPI == 4 || EPI == 5 || EPI == 8) {
                *reinterpret_cast<__half2*>(&outH[(long)row0 * N + col0]) =
                    __halves2half2(__float2half_rn(c0), __float2half_rn(c1));
                *reinterpret_cast<__half2*>(&outH[(long)(row0 + 8) * N + col0]) =
                    __halves2half2(__float2half_rn(c2), __float2half_rn(c3));
            } else {
                *reinterpret_cast<float2*>(&C[(long)row0 * N + col0]) = make_float2(c0, c1);
                *reinterpret_cast<float2*>(&C[(long)(row0 + 8) * N + col0]) = make_float2(c2, c3);
            }
        }

    if (EPI == 5) {
#pragma unroll
        for (int mi = 0; mi < 2; ++mi)
#pragma unroll
            for (int j = 0; j < 2; ++j) {
                rsum[mi][j] += __shfl_xor_sync(0xFFFFFFFFu, rsum[mi][j], 1);
                rsum[mi][j] += __shfl_xor_sync(0xFFFFFFFFu, rsum[mi][j], 2);
            }
        float* rowbuf = reinterpret_cast<float*>(sm);
        if (tid < 128) rowbuf[tid] = 0.0f;
        __syncthreads();
        if ((lane & 3) == 0) {
#pragma unroll
            for (int mi = 0; mi < 2; ++mi)
#pragma unroll
                for (int j = 0; j < 2; ++j)
                    atomicAdd(&rowbuf[warp_m * 32 + mi * 16 + (lane >> 2) + j * 8],
                              rsum[mi][j]);
        }
        __syncthreads();
        if (tid < 128)
            psum[(long)blockIdx.x * (B_ * S_) + (long)bz * S_ + bm + tid] = rowbuf[tid];
    }
}

// ---------------------------------------------------------------------------
// Z[row] = sum over 16 tile partials
// ---------------------------------------------------------------------------
__global__ void __launch_bounds__(256)
zreduce_kernel(const float* __restrict__ psum, float* __restrict__ z)
{
    const int i = blockIdx.x * 256 + threadIdx.x;
    float s = 0.0f;
#pragma unroll
    for (int k = 0; k < 16; ++k) s += psum[(long)k * (B_ * S_) + i];
    z[i] = s;
}

// ---------------------------------------------------------------------------
// fp32 -> fp16 casts: big x, and the 3 weights batched in one launch
// ---------------------------------------------------------------------------
__global__ void __launch_bounds__(256)
split_hi_kernel(const float* __restrict__ src, __half* __restrict__ hi, long n4)
{
    const long i = (long)blockIdx.x * blockDim.x + threadIdx.x;
    if (i >= n4) return;
    const float4 v = reinterpret_cast<const float4*>(src)[i];
    __half2* hi2 = reinterpret_cast<__half2*>(hi);
    hi2[2 * i]     = __halves2half2(__float2half_rn(v.x), __float2half_rn(v.y));
    hi2[2 * i + 1] = __halves2half2(__float2half_rn(v.z), __float2half_rn(v.w));
}

__global__ void __launch_bounds__(256)
split3_kernel(const float* __restrict__ w0, const float* __restrict__ w1,
              const float* __restrict__ w2, __half* __restrict__ h0,
              __half* __restrict__ h1, __half* __restrict__ h2, long n4)
{
    const long i = (long)blockIdx.x * blockDim.x + threadIdx.x;
    if (i >= n4) return;
    const float* src = (blockIdx.y == 0) ? w0 : (blockIdx.y == 1) ? w1 : w2;
    __half* dst      = (blockIdx.y == 0) ? h0 : (blockIdx.y == 1) ? h1 : h2;
    const float4 v = reinterpret_cast<const float4*>(src)[i];
    __half2* hi2 = reinterpret_cast<__half2*>(dst);
    hi2[2 * i]     = __halves2half2(__float2half_rn(v.x), __float2half_rn(v.y));
    hi2[2 * i + 1] = __halves2half2(__float2half_rn(v.z), __float2half_rn(v.w));
}

// ---------------------------------------------------------------------------
extern "C" void kernel_launch(void* const* d_in, const int* in_sizes, int n_in,
                              void* d_out, int out_size)
{
    const float* x    = (const float*)d_in[0];
    const int*   mask = (const int*)  d_in[1];
    const float* wq   = (const float*)d_in[2];
    const float* bq   = (const float*)d_in[3];
    const float* wk   = (const float*)d_in[4];
    const float* bk   = (const float*)d_in[5];
    const float* wv   = (const float*)d_in[6];
    const float* bv   = (const float*)d_in[7];
    float* out = (float*)d_out;

    float *psum, *gz;
    cudaGetSymbolAddress((void**)&psum, g_psum);
    cudaGetSymbolAddress((void**)&gz, g_Z);
    __half *xhi, *qhi, *khi, *vthi, *phi, *wqh, *wkh, *wvh;
    cudaGetSymbolAddress((void**)&xhi, g_xhi);
    cudaGetSymbolAddress((void**)&qhi, g_qhi);
    cudaGetSymbolAddress((void**)&khi, g_khi);
    cudaGetSymbolAddress((void**)&vthi, g_vthi);
    cudaGetSymbolAddress((void**)&phi, g_phi);
    cudaGetSymbolAddress((void**)&wqh, g_wqh);
    cudaGetSymbolAddress((void**)&wkh, g_wkh);
    cudaGetSymbolAddress((void**)&wvh, g_wvh);

    // dynamic smem > 48KB needs opt-in
    cudaFuncSetAttribute(gemm_f16s<8>, cudaFuncAttributeMaxDynamicSharedMemorySize, SMEM_SZ);
    cudaFuncSetAttribute(gemm_f16s<5>, cudaFuncAttributeMaxDynamicSharedMemorySize, SMEM_SZ);
    cudaFuncSetAttribute(gemm_f16s<6>, cudaFuncAttributeMaxDynamicSharedMemorySize, SMEM_SZ);
    cudaFuncSetAttribute(gemm_f16s<7>, cudaFuncAttributeMaxDynamicSharedMemorySize, SMEM_SZ);

    const long nx = (long)B_ * S_ * E_;
    const long nw = (long)E_ * E_;

    // 1) fp16 casts
    split_hi_kernel<<<(unsigned)((nx / 4 + 255) / 256), 256>>>(x, xhi, nx / 4);
    split3_kernel<<<dim3((unsigned)((nw / 4 + 255) / 256), 3), 256>>>(
        wq, wk, wv, wqh, wkh, wvh, nw / 4);

    // 2) projections (1-term): Q+K merged in one launch (z=0: Q, z=1: K); V fused transpose
    const dim3 gqk(E_ / 128, (B_ * S_) / 128, 2);
    gemm_f16s<8><<<gqk, 256, SMEM_SZ>>>(xhi, wqh, bq, nullptr, nullptr, qhi,
                                        nullptr, nullptr, wkh, bk, khi,
                                        E_, E_, 0, 0, 0, 1.0f);
    const dim3 gproj(E_ / 128, (B_ * S_) / 128, 1);
    gemm_f16s<7><<<gproj, 256, SMEM_SZ>>>(xhi, wvh, bv, nullptr, nullptr, vthi,
                                          nullptr, nullptr, nullptr, nullptr, nullptr,
                                          E_, E_, 0, 0, 0, 1.0f);

    // 3) scores + mask + max-free exp -> unnormalized P (fp16) + row partials
    const float scale = 0.044194173824159216f;  // 512^-0.5
    const dim3 gsc(S_ / 128, S_ / 128, B_);
    gemm_f16s<5><<<gsc, 256, SMEM_SZ>>>(qhi, khi, nullptr, mask, nullptr, phi,
                                        psum, nullptr, nullptr, nullptr, nullptr,
                                        E_, S_,
                                        (long)S_ * E_, (long)S_ * E_,
                                        (long)S_ * S_, scale);

    // 4) Z[row] = sum of partials
    zreduce_kernel<<<(B_ * S_) / 256, 256>>>(psum, gz);

    // 5) out = (P~ . Vt^T) / Z
    const dim3 gpv(E_ / 128, S_ / 128, B_);
    gemm_f16s<6><<<gpv, 256, SMEM_SZ>>>(phi, vthi, nullptr, nullptr, out, nullptr,
                                        nullptr, gz, nullptr, nullptr, nullptr,
                                        S_, E_,
                                        (long)S_ * S_, (long)E_ * S_,
                                        (long)S_ * E_, 1.0f);
}

// round 15
// speedup vs baseline: 1.1392x; 1.0610x over previous
#include <cuda_runtime.h>
#include <cuda_fp16.h>
#include <cstdint>

#define B_ 8
#define S_ 2048
#define E_ 512

// ---------------- scratch (__device__ globals; no allocs allowed) ----------
__device__ __align__(16) __half g_xhi[(size_t)B_ * S_ * E_];
__device__ __align__(16) __half g_qhi[(size_t)B_ * S_ * E_];
__device__ __align__(16) __half g_khi[(size_t)B_ * S_ * E_];
__device__ __align__(16) __half g_vthi[(size_t)B_ * E_ * S_];  // [B][E][S]
__device__ __align__(16) __half g_phi[(size_t)B_ * S_ * S_];   // unnormalized exp
__device__ __align__(16) __half g_wqh[E_ * E_];
__device__ __align__(16) __half g_wkh[E_ * E_];
__device__ __align__(16) __half g_wvh[E_ * E_];
__device__ __align__(16) float g_psum[16 * B_ * S_];           // [tileN][B*S]
__device__ __align__(16) float g_Z[B_ * S_];                   // row sums

// ---------------- helpers ---------------------------------------------------
__device__ __forceinline__ uint32_t smem_u32(const void* p) {
    uint32_t a;
    asm("{ .reg .u64 t; cvta.to.shared.u64 t, %1; cvt.u32.u64 %0, t; }"
        : "=r"(a) : "l"(p));
    return a;
}
__device__ __forceinline__ void cp16(uint32_t dst, const void* src) {
    asm volatile("cp.async.cg.shared.global [%0], [%1], 16;"
                 :: "r"(dst), "l"(src) : "memory");
}
__device__ __forceinline__ void cp_commit() {
    asm volatile("cp.async.commit_group;" ::: "memory");
}
template <int N>
__device__ __forceinline__ void cp_wait() {
    asm volatile("cp.async.wait_group %0;" :: "n"(N) : "memory");
}
__device__ __forceinline__ void ldm_x4(uint32_t& r0, uint32_t& r1, uint32_t& r2,
                                       uint32_t& r3, uint32_t addr) {
    asm volatile("ldmatrix.sync.aligned.m8n8.x4.shared.b16 {%0,%1,%2,%3}, [%4];"
                 : "=r"(r0), "=r"(r1), "=r"(r2), "=r"(r3) : "r"(addr));
}
__device__ __forceinline__ void mma16816(float* d, const uint32_t* a, const uint32_t* b) {
    asm volatile("mma.sync.aligned.m16n8k16.row.col.f32.f16.f16.f32 "
                 "{%0,%1,%2,%3}, {%4,%5,%6,%7}, {%8,%9}, {%0,%1,%2,%3};"
                 : "+f"(d[0]), "+f"(d[1]), "+f"(d[2]), "+f"(d[3])
                 : "r"(a[0]), "r"(a[1]), "r"(a[2]), "r"(a[3]), "r"(b[0]), "r"(b[1]));
}

// ---------------------------------------------------------------------------
// NT GEMM, pure fp16 MMA: C-tile = A[M,K] . B[N,K]^T (+ epilogue).
// Block 128x128, 8 warps (4m x 2n), warp tile 32x64, KC=64,
// THREE-stage cp.async pipeline, ONE __syncthreads per chunk.
// EPI: 4 = +bias -> fp16 outH
//      5 = p = (mask>0 ? 0 : exp(scale*s)) -> fp16 outH; row partial sums -> psum
//      6 = acc / Z[row] -> fp32 C
//      7 = +bias -> fp16, transposed into outH as [E][S] tile (V projection)
//      8 = QK merged: blockIdx.z selects (Bm0,bias0,out0) / (Bm1,bias1,out1)
// ---------------------------------------------------------------------------
#define KC 64
#define TSTR 72                        // padded halfs per smem row (64 + 8)
#define TILE_B (128 * TSTR * 2)        // 18432 bytes per tile
#define STAGE_B (2 * TILE_B)           // 36864
#define NSTAGE 3
#define SMEM_SZ (NSTAGE * STAGE_B)     // 110592

template <int EPI>
__global__ void __launch_bounds__(256)
gemm_f16s(const __half* __restrict__ A, const __half* __restrict__ Bm,
          const float* __restrict__ bias, const int* __restrict__ mask,
          float* __restrict__ C, __half* __restrict__ outH,
          float* __restrict__ psum, const float* __restrict__ zrow,
          const __half* __restrict__ Bm1, const float* __restrict__ bias1,
          __half* __restrict__ outH1,
          int K, int N, long sA, long sB, long sC, float scale)
{
    extern __shared__ __align__(16) char sm[];
    const uint32_t sb = smem_u32(sm);

    const int tid  = threadIdx.x;
    const int lane = tid & 31;
    const int wid  = tid >> 5;
    const int warp_m = wid & 3;
    const int warp_n = wid >> 2;

    const int bz = blockIdx.z;
    if (EPI == 8) {
        if (bz == 1) { Bm = Bm1; bias = bias1; outH = outH1; }
    } else {
        A  += (long)bz * sA;
        Bm += (long)bz * sB;
        if (EPI == 5) mask += (long)bz * sC;
        if (EPI == 6) C += (long)bz * sC;
        if (EPI == 5) outH += (long)bz * sC;
    }
    const int bm = blockIdx.y * 128;
    const int bn = blockIdx.x * 128;

    const int lr = tid >> 3;           // row 0..31 (4 passes -> 128)
    const int ls = tid & 7;            // 16B segment (8 per 128B row)
    auto load_chunk = [&](int c) {
        const uint32_t st = sb + (uint32_t)(c % NSTAGE) * STAGE_B;
        const int k0 = c * KC;
#pragma unroll
        for (int t = 0; t < 4; ++t) {
            const int r = lr + t * 32;
            const uint32_t so = (uint32_t)(r * (TSTR * 2) + ls * 16);
            cp16(st + so,          A  + (long)(bm + r) * K + k0 + ls * 8);
            cp16(st + TILE_B + so, Bm + (long)(bn + r) * K + k0 + ls * 8);
        }
        cp_commit();
    };

    float acc[2][8][4];
#pragma unroll
    for (int mi = 0; mi < 2; ++mi)
#pragma unroll
        for (int ni = 0; ni < 8; ++ni)
#pragma unroll
            for (int r = 0; r < 4; ++r) acc[mi][ni][r] = 0.0f;

    const int quad = lane >> 3, lm8 = lane & 7;
    const int a_row = warp_m * 32 + lm8 + (quad & 1) * 8;
    const int a_col = (quad >> 1) * 8;
    const int b_row = warp_n * 64 + lm8 + (quad >> 1) * 8;
    const int b_col = (quad & 1) * 8;

    const int nch = K / KC;            // >= 2 for all our shapes
    load_chunk(0);
    load_chunk(1);
    for (int c = 0; c < nch; ++c) {
        if (c == nch - 1) cp_wait<0>();
        else              cp_wait<1>();
        __syncthreads();

        const uint32_t st = sb + (uint32_t)(c % NSTAGE) * STAGE_B;
#pragma unroll
        for (int ks = 0; ks < KC; ks += 16) {
            uint32_t ah[2][4], bh[8][2];
#pragma unroll
            for (int mi = 0; mi < 2; ++mi) {
                const uint32_t ao =
                    (uint32_t)(((a_row + mi * 16) * TSTR + a_col + ks) * 2);
                ldm_x4(ah[mi][0], ah[mi][1], ah[mi][2], ah[mi][3], st + ao);
            }
#pragma unroll
            for (int np = 0; np < 4; ++np) {
                const uint32_t bo =
                    (uint32_t)(((b_row + np * 16) * TSTR + b_col + ks) * 2);
                ldm_x4(bh[2 * np][0], bh[2 * np][1], bh[2 * np + 1][0], bh[2 * np + 1][1],
                       st + TILE_B + bo);
            }
#pragma unroll
            for (int mi = 0; mi < 2; ++mi)
#pragma unroll
                for (int ni = 0; ni < 8; ++ni)
                    mma16816(acc[mi][ni], ah[mi], bh[ni]);
        }
        if (c + 2 < nch) load_chunk(c + 2);
    }

    // ---- epilogue ----
    if (EPI == 7) {
        // V projection: +bias, fp16, transpose via smem, coalesced Vt writes.
        __syncthreads();               // all warps done reading stage buffers
        __half* buf = reinterpret_cast<__half*>(sm);
#pragma unroll
        for (int mi = 0; mi < 2; ++mi)
#pragma unroll
            for (int ni = 0; ni < 8; ++ni) {
                const int rl = warp_m * 32 + mi * 16 + (lane >> 2);
                const int cl = warp_n * 64 + ni * 8 + (lane & 3) * 2;
                const float2 bb = *reinterpret_cast<const float2*>(&bias[bn + cl]);
                const float c0 = acc[mi][ni][0] + bb.x;
                const float c1 = acc[mi][ni][1] + bb.y;
                const float c2 = acc[mi][ni][2] + bb.x;
                const float c3 = acc[mi][ni][3] + bb.y;
                *reinterpret_cast<__half2*>(&buf[rl * 136 + cl]) =
                    __halves2half2(__float2half_rn(c0), __float2half_rn(c1));
                *reinterpret_cast<__half2*>(&buf[(rl + 8) * 136 + cl]) =
                    __halves2half2(__float2half_rn(c2), __float2half_rn(c3));
            }
        __syncthreads();
        const int b  = bm / S_;
        const int s0 = bm % S_;
#pragma unroll
        for (int i = 0; i < 32; ++i) {
            const int idx = tid + i * 256;     // 8192 half2 units
            const int e  = idx >> 6;           // 0..127
            const int sp = idx & 63;           // half2 index along s
            const __half2 v = __halves2half2(buf[(2 * sp) * 136 + e],
                                             buf[(2 * sp + 1) * 136 + e]);
            *reinterpret_cast<__half2*>(
                &outH[((long)b * E_ + bn + e) * S_ + s0 + 2 * sp]) = v;
        }
        return;
    }

    float invz[2][2];
    if (EPI == 6) {
#pragma unroll
        for (int mi = 0; mi < 2; ++mi)
#pragma unroll
            for (int j = 0; j < 2; ++j) {
                const int row = bm + warp_m * 32 + mi * 16 + (lane >> 2) + j * 8;
                invz[mi][j] = 1.0f / __ldg(&zrow[(long)bz * S_ + row]);
            }
    }
    float rsum[2][2] = {{0.0f, 0.0f}, {0.0f, 0.0f}};

#pragma unroll
    for (int mi = 0; mi < 2; ++mi)
#pragma unroll
        for (int ni = 0; ni < 8; ++ni) {
            const int row0 = bm + warp_m * 32 + mi * 16 + (lane >> 2);
            const int col0 = bn + warp_n * 64 + ni * 8 + (lane & 3) * 2;
            float c0 = acc[mi][ni][0], c1 = acc[mi][ni][1];
            float c2 = acc[mi][ni][2], c3 = acc[mi][ni][3];
            if (EPI == 4 || EPI == 8) {
                const float2 bb = *reinterpret_cast<const float2*>(&bias[col0]);
                c0 += bb.x; c1 += bb.y; c2 += bb.x; c3 += bb.y;
            }
            if (EPI == 5) {
                const int2 ma = *reinterpret_cast<const int2*>(&mask[(long)row0 * N + col0]);
                const int2 mb = *reinterpret_cast<const int2*>(&mask[(long)(row0 + 8) * N + col0]);
                c0 = (ma.x > 0) ? 0.0f : __expf(scale * c0);
                c1 = (ma.y > 0) ? 0.0f : __expf(scale * c1);
                c2 = (mb.x > 0) ? 0.0f : __expf(scale * c2);
                c3 = (mb.y > 0) ? 0.0f : __expf(scale * c3);
                rsum[mi][0] += c0 + c1;
                rsum[mi][1] += c2 + c3;
            }
            if (EPI == 6) {
                c0 *= invz[mi][0]; c1 *= invz[mi][0];
                c2 *= invz[mi][1]; c3 *= invz[mi][1];
            }
            if (EPI == 4 || EPI == 5 || EPI == 8) {
                *reinterpret_cast<__half2*>(&outH[(long)row0 * N + col0]) =
                    __halves2half2(__float2half_rn(c0), __float2half_rn(c1));
                *reinterpret_cast<__half2*>(&outH[(long)(row0 + 8) * N + col0]) =
                    __halves2half2(__float2half_rn(c2), __float2half_rn(c3));
            } else {
                *reinterpret_cast<float2*>(&C[(long)row0 * N + col0]) = make_float2(c0, c1);
                *reinterpret_cast<float2*>(&C[(long)(row0 + 8) * N + col0]) = make_float2(c2, c3);
            }
        }

    if (EPI == 5) {
#pragma unroll
        for (int mi = 0; mi < 2; ++mi)
#pragma unroll
            for (int j = 0; j < 2; ++j) {
                rsum[mi][j] += __shfl_xor_sync(0xFFFFFFFFu, rsum[mi][j], 1);
                rsum[mi][j] += __shfl_xor_sync(0xFFFFFFFFu, rsum[mi][j], 2);
            }
        __syncthreads();               // stage buffers no longer being read
        float* rowbuf = reinterpret_cast<float*>(sm);
        if (tid < 128) rowbuf[tid] = 0.0f;
        __syncthreads();
        if ((lane & 3) == 0) {
#pragma unroll
            for (int mi = 0; mi < 2; ++mi)
#pragma unroll
                for (int j = 0; j < 2; ++j)
                    atomicAdd(&rowbuf[warp_m * 32 + mi * 16 + (lane >> 2) + j * 8],
                              rsum[mi][j]);
        }
        __syncthreads();
        if (tid < 128)
            psum[(long)blockIdx.x * (B_ * S_) + (long)bz * S_ + bm + tid] = rowbuf[tid];
    }
}

// ---------------------------------------------------------------------------
// Z[row] = sum over 16 tile partials
// ---------------------------------------------------------------------------
__global__ void __launch_bounds__(256)
zreduce_kernel(const float* __restrict__ psum, float* __restrict__ z)
{
    const int i = blockIdx.x * 256 + threadIdx.x;
    float s = 0.0f;
#pragma unroll
    for (int k = 0; k < 16; ++k) s += psum[(long)k * (B_ * S_) + i];
    z[i] = s;
}

// ---------------------------------------------------------------------------
// fp32 -> fp16 casts: big x, and the 3 weights batched in one launch
// ---------------------------------------------------------------------------
__global__ void __launch_bounds__(256)
split_hi_kernel(const float* __restrict__ src, __half* __restrict__ hi, long n4)
{
    const long i = (long)blockIdx.x * blockDim.x + threadIdx.x;
    if (i >= n4) return;
    const float4 v = reinterpret_cast<const float4*>(src)[i];
    __half2* hi2 = reinterpret_cast<__half2*>(hi);
    hi2[2 * i]     = __halves2half2(__float2half_rn(v.x), __float2half_rn(v.y));
    hi2[2 * i + 1] = __halves2half2(__float2half_rn(v.z), __float2half_rn(v.w));
}

__global__ void __launch_bounds__(256)
split3_kernel(const float* __restrict__ w0, const float* __restrict__ w1,
              const float* __restrict__ w2, __half* __restrict__ h0,
              __half* __restrict__ h1, __half* __restrict__ h2, long n4)
{
    const long i = (long)blockIdx.x * blockDim.x + threadIdx.x;
    if (i >= n4) return;
    const float* src = (blockIdx.y == 0) ? w0 : (blockIdx.y == 1) ? w1 : w2;
    __half* dst      = (blockIdx.y == 0) ? h0 : (blockIdx.y == 1) ? h1 : h2;
    const float4 v = reinterpret_cast<const float4*>(src)[i];
    __half2* hi2 = reinterpret_cast<__half2*>(dst);
    hi2[2 * i]     = __halves2half2(__float2half_rn(v.x), __float2half_rn(v.y));
    hi2[2 * i + 1] = __halves2half2(__float2half_rn(v.z), __float2half_rn(v.w));
}

// ---------------------------------------------------------------------------
extern "C" void kernel_launch(void* const* d_in, const int* in_sizes, int n_in,
                              void* d_out, int out_size)
{
    const float* x    = (const float*)d_in[0];
    const int*   mask = (const int*)  d_in[1];
    const float* wq   = (const float*)d_in[2];
    const float* bq   = (const float*)d_in[3];
    const float* wk   = (const float*)d_in[4];
    const float* bk   = (const float*)d_in[5];
    const float* wv   = (const float*)d_in[6];
    const float* bv   = (const float*)d_in[7];
    float* out = (float*)d_out;

    float *psum, *gz;
    cudaGetSymbolAddress((void**)&psum, g_psum);
    cudaGetSymbolAddress((void**)&gz, g_Z);
    __half *xhi, *qhi, *khi, *vthi, *phi, *wqh, *wkh, *wvh;
    cudaGetSymbolAddress((void**)&xhi, g_xhi);
    cudaGetSymbolAddress((void**)&qhi, g_qhi);
    cudaGetSymbolAddress((void**)&khi, g_khi);
    cudaGetSymbolAddress((void**)&vthi, g_vthi);
    cudaGetSymbolAddress((void**)&phi, g_phi);
    cudaGetSymbolAddress((void**)&wqh, g_wqh);
    cudaGetSymbolAddress((void**)&wkh, g_wkh);
    cudaGetSymbolAddress((void**)&wvh, g_wvh);

    // dynamic smem > 48KB needs opt-in
    cudaFuncSetAttribute(gemm_f16s<8>, cudaFuncAttributeMaxDynamicSharedMemorySize, SMEM_SZ);
    cudaFuncSetAttribute(gemm_f16s<5>, cudaFuncAttributeMaxDynamicSharedMemorySize, SMEM_SZ);
    cudaFuncSetAttribute(gemm_f16s<6>, cudaFuncAttributeMaxDynamicSharedMemorySize, SMEM_SZ);
    cudaFuncSetAttribute(gemm_f16s<7>, cudaFuncAttributeMaxDynamicSharedMemorySize, SMEM_SZ);

    const long nx = (long)B_ * S_ * E_;
    const long nw = (long)E_ * E_;

    // 1) fp16 casts
    split_hi_kernel<<<(unsigned)((nx / 4 + 255) / 256), 256>>>(x, xhi, nx / 4);
    split3_kernel<<<dim3((unsigned)((nw / 4 + 255) / 256), 3), 256>>>(
        wq, wk, wv, wqh, wkh, wvh, nw / 4);

    // 2) projections: Q+K merged (z=0: Q, z=1: K); V fused transpose
    const dim3 gqk(E_ / 128, (B_ * S_) / 128, 2);
    gemm_f16s<8><<<gqk, 256, SMEM_SZ>>>(xhi, wqh, bq, nullptr, nullptr, qhi,
                                        nullptr, nullptr, wkh, bk, khi,
                                        E_, E_, 0, 0, 0, 1.0f);
    const dim3 gproj(E_ / 128, (B_ * S_) / 128, 1);
    gemm_f16s<7><<<gproj, 256, SMEM_SZ>>>(xhi, wvh, bv, nullptr, nullptr, vthi,
                                          nullptr, nullptr, nullptr, nullptr, nullptr,
                                          E_, E_, 0, 0, 0, 1.0f);

    // 3) scores + mask + max-free exp -> unnormalized P (fp16) + row partials
    const float scale = 0.044194173824159216f;  // 512^-0.5
    const dim3 gsc(S_ / 128, S_ / 128, B_);
    gemm_f16s<5><<<gsc, 256, SMEM_SZ>>>(qhi, khi, nullptr, mask, nullptr, phi,
                                        psum, nullptr, nullptr, nullptr, nullptr,
                                        E_, S_,
                                        (long)S_ * E_, (long)S_ * E_,
                                        (long)S_ * S_, scale);

    // 4) Z[row] = sum of partials
    zreduce_kernel<<<(B_ * S_) / 256, 256>>>(psum, gz);

    // 5) out = (P~ . Vt^T) / Z
    const dim3 gpv(E_ / 128, S_ / 128, B_);
    gemm_f16s<6><<<gpv, 256, SMEM_SZ>>>(phi, vthi, nullptr, nullptr, out, nullptr,
                                        nullptr, gz, nullptr, nullptr, nullptr,
                                        S_, E_,
                                        (long)S_ * S_, (long)E_ * S_,
                                        (long)S_ * E_, 1.0f);
}

// round 17
// speedup vs baseline: 1.1726x; 1.0293x over previous
#include <cuda_runtime.h>
#include <cuda_fp16.h>
#include <cstdint>

#define B_ 8
#define S_ 2048
#define E_ 512

// ---------------- scratch (__device__ globals; no allocs allowed) ----------
__device__ __align__(16) __half g_xhi[(size_t)B_ * S_ * E_];
__device__ __align__(16) __half g_qhi[(size_t)B_ * S_ * E_];
__device__ __align__(16) __half g_khi[(size_t)B_ * S_ * E_];
__device__ __align__(16) __half g_vthi[(size_t)B_ * E_ * S_];  // [B][E][S]
__device__ __align__(16) __half g_phi[(size_t)B_ * S_ * S_];   // unnormalized exp
__device__ __align__(16) __half g_wqh[E_ * E_];
__device__ __align__(16) __half g_wkh[E_ * E_];
__device__ __align__(16) __half g_wvh[E_ * E_];
__device__ __align__(16) float g_psum[16 * B_ * S_];           // [tileN][B*S]

// ---------------- helpers ---------------------------------------------------
__device__ __forceinline__ uint32_t smem_u32(const void* p) {
    uint32_t a;
    asm("{ .reg .u64 t; cvta.to.shared.u64 t, %1; cvt.u32.u64 %0, t; }"
        : "=r"(a) : "l"(p));
    return a;
}
__device__ __forceinline__ void cp16(uint32_t dst, const void* src) {
    asm volatile("cp.async.cg.shared.global [%0], [%1], 16;"
                 :: "r"(dst), "l"(src) : "memory");
}
__device__ __forceinline__ void cp_commit() {
    asm volatile("cp.async.commit_group;" ::: "memory");
}
template <int N>
__device__ __forceinline__ void cp_wait() {
    asm volatile("cp.async.wait_group %0;" :: "n"(N) : "memory");
}
__device__ __forceinline__ void ldm_x4(uint32_t& r0, uint32_t& r1, uint32_t& r2,
                                       uint32_t& r3, uint32_t addr) {
    asm volatile("ldmatrix.sync.aligned.m8n8.x4.shared.b16 {%0,%1,%2,%3}, [%4];"
                 : "=r"(r0), "=r"(r1), "=r"(r2), "=r"(r3) : "r"(addr));
}
__device__ __forceinline__ void mma16816(float* d, const uint32_t* a, const uint32_t* b) {
    asm volatile("mma.sync.aligned.m16n8k16.row.col.f32.f16.f16.f32 "
                 "{%0,%1,%2,%3}, {%4,%5,%6,%7}, {%8,%9}, {%0,%1,%2,%3};"
                 : "+f"(d[0]), "+f"(d[1]), "+f"(d[2]), "+f"(d[3])
                 : "r"(a[0]), "r"(a[1]), "r"(a[2]), "r"(a[3]), "r"(b[0]), "r"(b[1]));
}

// ---------------------------------------------------------------------------
// NT GEMM, pure fp16 MMA: C-tile = A[M,K] . B[N,K]^T (+ epilogue).
// Block 128x128, 8 warps (4m x 2n), warp tile 32x64, KC=64,
// THREE-stage cp.async pipeline, ONE __syncthreads per chunk.
// EPI: 5 = p = (mask>0 ? 0 : exp(scale*s)) -> fp16 outH; row partial sums -> psum
//      6 = acc / Z[row] -> fp32 C, Z computed in-epilogue from psum partials
//      8 = merged projections: z=0 Q(+bias->fp16), z=1 K(+bias->fp16),
//          z=2 V(+bias->fp16 transposed into [E][S])
// ---------------------------------------------------------------------------
#define KC 64
#define TSTR 72                        // padded halfs per smem row (64 + 8)
#define TILE_B (128 * TSTR * 2)        // 18432 bytes per tile
#define STAGE_B (2 * TILE_B)           // 36864
#define NSTAGE 3
#define SMEM_SZ (NSTAGE * STAGE_B)     // 110592

template <int EPI>
__global__ void __launch_bounds__(256)
gemm_f16s(const __half* __restrict__ A, const __half* __restrict__ Bm,
          const float* __restrict__ bias, const int* __restrict__ mask,
          float* __restrict__ C, __half* __restrict__ outH,
          float* __restrict__ psum,
          const __half* __restrict__ Bm1, const float* __restrict__ bias1,
          __half* __restrict__ outH1,
          const __half* __restrict__ Bm2, const float* __restrict__ bias2,
          __half* __restrict__ outH2,
          int K, int N, long sA, long sB, long sC, float scale)
{
    extern __shared__ __align__(16) char sm[];
    const uint32_t sb = smem_u32(sm);

    const int tid  = threadIdx.x;
    const int lane = tid & 31;
    const int wid  = tid >> 5;
    const int warp_m = wid & 3;
    const int warp_n = wid >> 2;

    const int bz = blockIdx.z;
    if (EPI == 8) {
        if (bz == 1)      { Bm = Bm1; bias = bias1; outH = outH1; }
        else if (bz == 2) { Bm = Bm2; bias = bias2; outH = outH2; }
    } else {
        A  += (long)bz * sA;
        Bm += (long)bz * sB;
        if (EPI == 5) mask += (long)bz * sC;
        if (EPI == 6) C += (long)bz * sC;
        if (EPI == 5) outH += (long)bz * sC;
    }
    const int bm = blockIdx.y * 128;
    const int bn = blockIdx.x * 128;

    const int lr = tid >> 3;           // row 0..31 (4 passes -> 128)
    const int ls = tid & 7;            // 16B segment (8 per 128B row)
    auto load_chunk = [&](int c) {
        const uint32_t st = sb + (uint32_t)(c % NSTAGE) * STAGE_B;
        const int k0 = c * KC;
#pragma unroll
        for (int t = 0; t < 4; ++t) {
            const int r = lr + t * 32;
            const uint32_t so = (uint32_t)(r * (TSTR * 2) + ls * 16);
            cp16(st + so,          A  + (long)(bm + r) * K + k0 + ls * 8);
            cp16(st + TILE_B + so, Bm + (long)(bn + r) * K + k0 + ls * 8);
        }
        cp_commit();
    };

    float acc[2][8][4];
#pragma unroll
    for (int mi = 0; mi < 2; ++mi)
#pragma unroll
        for (int ni = 0; ni < 8; ++ni)
#pragma unroll
            for (int r = 0; r < 4; ++r) acc[mi][ni][r] = 0.0f;

    const int quad = lane >> 3, lm8 = lane & 7;
    const int a_row = warp_m * 32 + lm8 + (quad & 1) * 8;
    const int a_col = (quad >> 1) * 8;
    const int b_row = warp_n * 64 + lm8 + (quad >> 1) * 8;
    const int b_col = (quad & 1) * 8;

    const int nch = K / KC;            // >= 2 for all our shapes
    load_chunk(0);
    load_chunk(1);
    for (int c = 0; c < nch; ++c) {
        if (c == nch - 1) cp_wait<0>();
        else              cp_wait<1>();
        __syncthreads();

        const uint32_t st = sb + (uint32_t)(c % NSTAGE) * STAGE_B;
#pragma unroll
        for (int ks = 0; ks < KC; ks += 16) {
            uint32_t ah[2][4], bh[8][2];
#pragma unroll
            for (int mi = 0; mi < 2; ++mi) {
                const uint32_t ao =
                    (uint32_t)(((a_row + mi * 16) * TSTR + a_col + ks) * 2);
                ldm_x4(ah[mi][0], ah[mi][1], ah[mi][2], ah[mi][3], st + ao);
            }
#pragma unroll
            for (int np = 0; np < 4; ++np) {
                const uint32_t bo =
                    (uint32_t)(((b_row + np * 16) * TSTR + b_col + ks) * 2);
                ldm_x4(bh[2 * np][0], bh[2 * np][1], bh[2 * np + 1][0], bh[2 * np + 1][1],
                       st + TILE_B + bo);
            }
#pragma unroll
            for (int mi = 0; mi < 2; ++mi)
#pragma unroll
                for (int ni = 0; ni < 8; ++ni)
                    mma16816(acc[mi][ni], ah[mi], bh[ni]);
        }
        if (c + 2 < nch) load_chunk(c + 2);
    }

    // ---- epilogue ----
    if (EPI == 8 && bz == 2) {
        // V projection: +bias, fp16, transpose via smem, coalesced Vt writes.
        __syncthreads();               // all warps done reading stage buffers
        __half* buf = reinterpret_cast<__half*>(sm);
#pragma unroll
        for (int mi = 0; mi < 2; ++mi)
#pragma unroll
            for (int ni = 0; ni < 8; ++ni) {
                const int rl = warp_m * 32 + mi * 16 + (lane >> 2);
                const int cl = warp_n * 64 + ni * 8 + (lane & 3) * 2;
                const float2 bb = *reinterpret_cast<const float2*>(&bias[bn + cl]);
                const float c0 = acc[mi][ni][0] + bb.x;
                const float c1 = acc[mi][ni][1] + bb.y;
                const float c2 = acc[mi][ni][2] + bb.x;
                const float c3 = acc[mi][ni][3] + bb.y;
                *reinterpret_cast<__half2*>(&buf[rl * 136 + cl]) =
                    __halves2half2(__float2half_rn(c0), __float2half_rn(c1));
                *reinterpret_cast<__half2*>(&buf[(rl + 8) * 136 + cl]) =
                    __halves2half2(__float2half_rn(c2), __float2half_rn(c3));
            }
        __syncthreads();
        const int b  = bm / S_;
        const int s0 = bm % S_;
#pragma unroll
        for (int i = 0; i < 32; ++i) {
            const int idx = tid + i * 256;     // 8192 half2 units
            const int e  = idx >> 6;           // 0..127
            const int sp = idx & 63;           // half2 index along s
            const __half2 v = __halves2half2(buf[(2 * sp) * 136 + e],
                                             buf[(2 * sp + 1) * 136 + e]);
            *reinterpret_cast<__half2*>(
                &outH[((long)b * E_ + bn + e) * S_ + s0 + 2 * sp]) = v;
        }
        return;
    }

    float invz[2][2];
    if (EPI == 6) {
        // fold Z reduction here: rows bm..bm+127, same k-ascending order as the
        // old zreduce kernel (bit-identical sums).
        __syncthreads();               // stage buffers no longer being read
        float* rowbuf = reinterpret_cast<float*>(sm);
        if (tid < 128) {
            float s = 0.0f;
#pragma unroll
            for (int k = 0; k < 16; ++k)
                s += psum[(long)k * (B_ * S_) + (long)bz * S_ + bm + tid];
            rowbuf[tid] = 1.0f / s;
        }
        __syncthreads();
#pragma unroll
        for (int mi = 0; mi < 2; ++mi)
#pragma unroll
            for (int j = 0; j < 2; ++j)
                invz[mi][j] = rowbuf[warp_m * 32 + mi * 16 + (lane >> 2) + j * 8];
    }
    float rsum[2][2] = {{0.0f, 0.0f}, {0.0f, 0.0f}};

#pragma unroll
    for (int mi = 0; mi < 2; ++mi)
#pragma unroll
        for (int ni = 0; ni < 8; ++ni) {
            const int row0 = bm + warp_m * 32 + mi * 16 + (lane >> 2);
            const int col0 = bn + warp_n * 64 + ni * 8 + (lane & 3) * 2;
            float c0 = acc[mi][ni][0], c1 = acc[mi][ni][1];
            float c2 = acc[mi][ni][2], c3 = acc[mi][ni][3];
            if (EPI == 8) {
                const float2 bb = *reinterpret_cast<const float2*>(&bias[col0]);
                c0 += bb.x; c1 += bb.y; c2 += bb.x; c3 += bb.y;
            }
            if (EPI == 5) {
                const int2 ma = *reinterpret_cast<const int2*>(&mask[(long)row0 * N + col0]);
                const int2 mb = *reinterpret_cast<const int2*>(&mask[(long)(row0 + 8) * N + col0]);
                c0 = (ma.x > 0) ? 0.0f : __expf(scale * c0);
                c1 = (ma.y > 0) ? 0.0f : __expf(scale * c1);
                c2 = (mb.x > 0) ? 0.0f : __expf(scale * c2);
                c3 = (mb.y > 0) ? 0.0f : __expf(scale * c3);
                rsum[mi][0] += c0 + c1;
                rsum[mi][1] += c2 + c3;
            }
            if (EPI == 6) {
                c0 *= invz[mi][0]; c1 *= invz[mi][0];
                c2 *= invz[mi][1]; c3 *= invz[mi][1];
            }
            if (EPI == 8 || EPI == 5) {
                *reinterpret_cast<__half2*>(&outH[(long)row0 * N + col0]) =
                    __halves2half2(__float2half_rn(c0), __float2half_rn(c1));
                *reinterpret_cast<__half2*>(&outH[(long)(row0 + 8) * N + col0]) =
                    __halves2half2(__float2half_rn(c2), __float2half_rn(c3));
            } else {
                *reinterpret_cast<float2*>(&C[(long)row0 * N + col0]) = make_float2(c0, c1);
                *reinterpret_cast<float2*>(&C[(long)(row0 + 8) * N + col0]) = make_float2(c2, c3);
            }
        }

    if (EPI == 5) {
#pragma unroll
        for (int mi = 0; mi < 2; ++mi)
#pragma unroll
            for (int j = 0; j < 2; ++j) {
                rsum[mi][j] += __shfl_xor_sync(0xFFFFFFFFu, rsum[mi][j], 1);
                rsum[mi][j] += __shfl_xor_sync(0xFFFFFFFFu, rsum[mi][j], 2);
            }
        __syncthreads();               // stage buffers no longer being read
        float* rowbuf = reinterpret_cast<float*>(sm);
        if (tid < 128) rowbuf[tid] = 0.0f;
        __syncthreads();
        if ((lane & 3) == 0) {
#pragma unroll
            for (int mi = 0; mi < 2; ++mi)
#pragma unroll
                for (int j = 0; j < 2; ++j)
                    atomicAdd(&rowbuf[warp_m * 32 + mi * 16 + (lane >> 2) + j * 8],
                              rsum[mi][j]);
        }
        __syncthreads();
        if (tid < 128)
            psum[(long)blockIdx.x * (B_ * S_) + (long)bz * S_ + bm + tid] = rowbuf[tid];
    }
}

// ---------------------------------------------------------------------------
// fp32 -> fp16 casts: big x, and the 3 weights batched in one launch
// ---------------------------------------------------------------------------
__global__ void __launch_bounds__(256)
split_hi_kernel(const float* __restrict__ src, __half* __restrict__ hi, long n4)
{
    const long i = (long)blockIdx.x * blockDim.x + threadIdx.x;
    if (i >= n4) return;
    const float4 v = reinterpret_cast<const float4*>(src)[i];
    __half2* hi2 = reinterpret_cast<__half2*>(hi);
    hi2[2 * i]     = __halves2half2(__float2half_rn(v.x), __float2half_rn(v.y));
    hi2[2 * i + 1] = __halves2half2(__float2half_rn(v.z), __float2half_rn(v.w));
}

__global__ void __launch_bounds__(256)
split3_kernel(const float* __restrict__ w0, const float* __restrict__ w1,
              const float* __restrict__ w2, __half* __restrict__ h0,
              __half* __restrict__ h1, __half* __restrict__ h2, long n4)
{
    const long i = (long)blockIdx.x * blockDim.x + threadIdx.x;
    if (i >= n4) return;
    const float* src = (blockIdx.y == 0) ? w0 : (blockIdx.y == 1) ? w1 : w2;
    __half* dst      = (blockIdx.y == 0) ? h0 : (blockIdx.y == 1) ? h1 : h2;
    const float4 v = reinterpret_cast<const float4*>(src)[i];
    __half2* hi2 = reinterpret_cast<__half2*>(dst);
    hi2[2 * i]     = __halves2half2(__float2half_rn(v.x), __float2half_rn(v.y));
    hi2[2 * i + 1] = __halves2half2(__float2half_rn(v.z), __float2half_rn(v.w));
}

// ---------------------------------------------------------------------------
extern "C" void kernel_launch(void* const* d_in, const int* in_sizes, int n_in,
                              void* d_out, int out_size)
{
    const float* x    = (const float*)d_in[0];
    const int*   mask = (const int*)  d_in[1];
    const float* wq   = (const float*)d_in[2];
    const float* bq   = (const float*)d_in[3];
    const float* wk   = (const float*)d_in[4];
    const float* bk   = (const float*)d_in[5];
    const float* wv   = (const float*)d_in[6];
    const float* bv   = (const float*)d_in[7];
    float* out = (float*)d_out;

    float *psum;
    cudaGetSymbolAddress((void**)&psum, g_psum);
    __half *xhi, *qhi, *khi, *vthi, *phi, *wqh, *wkh, *wvh;
    cudaGetSymbolAddress((void**)&xhi, g_xhi);
    cudaGetSymbolAddress((void**)&qhi, g_qhi);
    cudaGetSymbolAddress((void**)&khi, g_khi);
    cudaGetSymbolAddress((void**)&vthi, g_vthi);
    cudaGetSymbolAddress((void**)&phi, g_phi);
    cudaGetSymbolAddress((void**)&wqh, g_wqh);
    cudaGetSymbolAddress((void**)&wkh, g_wkh);
    cudaGetSymbolAddress((void**)&wvh, g_wvh);

    // dynamic smem > 48KB needs opt-in
    cudaFuncSetAttribute(gemm_f16s<8>, cudaFuncAttributeMaxDynamicSharedMemorySize, SMEM_SZ);
    cudaFuncSetAttribute(gemm_f16s<5>, cudaFuncAttributeMaxDynamicSharedMemorySize, SMEM_SZ);
    cudaFuncSetAttribute(gemm_f16s<6>, cudaFuncAttributeMaxDynamicSharedMemorySize, SMEM_SZ);

    const long nx = (long)B_ * S_ * E_;
    const long nw = (long)E_ * E_;

    // 1) fp16 casts
    split_hi_kernel<<<(unsigned)((nx / 4 + 255) / 256), 256>>>(x, xhi, nx / 4);
    split3_kernel<<<dim3((unsigned)((nw / 4 + 255) / 256), 3), 256>>>(
        wq, wk, wv, wqh, wkh, wvh, nw / 4);

    // 2) projections: Q, K, V merged in ONE launch (z=0 Q, z=1 K, z=2 V-transposed)
    const dim3 gproj(E_ / 128, (B_ * S_) / 128, 3);
    gemm_f16s<8><<<gproj, 256, SMEM_SZ>>>(xhi, wqh, bq, nullptr, nullptr, qhi,
                                          nullptr, wkh, bk, khi, wvh, bv, vthi,
                                          E_, E_, 0, 0, 0, 1.0f);

    // 3) scores + mask + max-free exp -> unnormalized P (fp16) + row partials
    const float scale = 0.044194173824159216f;  // 512^-0.5
    const dim3 gsc(S_ / 128, S_ / 128, B_);
    gemm_f16s<5><<<gsc, 256, SMEM_SZ>>>(qhi, khi, nullptr, mask, nullptr, phi,
                                        psum, nullptr, nullptr, nullptr,
                                        nullptr, nullptr, nullptr,
                                        E_, S_,
                                        (long)S_ * E_, (long)S_ * E_,
                                        (long)S_ * S_, scale);

    // 4) out = (P~ . Vt^T) / Z, Z folded into epilogue from psum partials
    const dim3 gpv(E_ / 128, S_ / 128, B_);
    gemm_f16s<6><<<gpv, 256, SMEM_SZ>>>(phi, vthi, nullptr, nullptr, out, nullptr,
                                        psum, nullptr, nullptr, nullptr,
                                        nullptr, nullptr, nullptr,
                                        S_, E_,
                                        (long)S_ * S_, (long)E_ * S_,
                                        (long)S_ * E_, 1.0f);
}